// round 4
// baseline (speedup 1.0000x reference)
#include <cuda_runtime.h>

#define N_NODES 100000
#define N_EDGES 1600000
#define IN_DIM  128
#define OUT_DIM 64

// Scratch (no allocations allowed).
__device__ float g_h[(size_t)N_NODES * OUT_DIM];   // 25.6 MB
__device__ float g_dis[N_NODES];
__device__ int   g_row[N_EDGES];                   // 6.4 MB
__device__ int   g_col[N_EDGES];                   // 6.4 MB
__device__ int   g_is64;                           // 1 = edge_index is int64

// ---------------------------------------------------------------------------
// 0) init flag + zero output accumulator + degree buffer
// ---------------------------------------------------------------------------
__global__ void zero_kernel(float* __restrict__ out) {
    int i = blockIdx.x * blockDim.x + threadIdx.x;
    int stride = gridDim.x * blockDim.x;
    if (i == 0) g_is64 = 1;
    const int out4 = N_NODES * OUT_DIM / 4;
    for (int idx = i; idx < out4; idx += stride)
        ((float4*)out)[idx] = make_float4(0.f, 0.f, 0.f, 0.f);
    for (int idx = i; idx < N_NODES; idx += stride)
        g_dis[idx] = 0.f;
}

// ---------------------------------------------------------------------------
// 0b) dtype detection: interpret first N_EDGES int64 slots as int32 pairs
//     (2*N_EDGES int32 reads = 12.8 MB, in bounds for EITHER dtype).
//     True int64 indices < 100000 have high word == 0; random int32 data
//     has nonzero odd words with overwhelming probability.
// ---------------------------------------------------------------------------
__global__ void detect_kernel(const int* __restrict__ ei32) {
    int e = blockIdx.x * blockDim.x + threadIdx.x;
    if (e >= N_EDGES) return;
    int hi = __ldg(&ei32[2 * e + 1]);
    if (hi != 0) g_is64 = 0;          // racy but monotonic: only writes 0
}

// ---------------------------------------------------------------------------
// 0c) materialize int32 row/col arrays under the detected interpretation
// ---------------------------------------------------------------------------
__global__ void convert_kernel(const void* __restrict__ ei) {
    int e = blockIdx.x * blockDim.x + threadIdx.x;
    if (e >= N_EDGES) return;
    if (g_is64) {
        const long long* p = (const long long*)ei;
        g_row[e] = (int)__ldg(&p[e]);
        g_col[e] = (int)__ldg(&p[N_EDGES + e]);
    } else {
        const int* p = (const int*)ei;
        g_row[e] = __ldg(&p[e]);
        g_col[e] = __ldg(&p[N_EDGES + e]);
    }
}

// ---------------------------------------------------------------------------
// 1) degree at targets (col)
// ---------------------------------------------------------------------------
__global__ void degree_kernel() {
    int e = blockIdx.x * blockDim.x + threadIdx.x;
    if (e >= N_EDGES) return;
    atomicAdd(&g_dis[g_col[e]], 1.0f);
}

// ---------------------------------------------------------------------------
// 2) deg -> deg^{-1/2} in place
// ---------------------------------------------------------------------------
__global__ void finalize_deg_kernel() {
    int i = blockIdx.x * blockDim.x + threadIdx.x;
    if (i >= N_NODES) return;
    float d = g_dis[i];
    g_dis[i] = (d > 0.f) ? rsqrtf(d) : 0.f;
}

// ---------------------------------------------------------------------------
// 3) GEMM: h[N,64] = x[N,128] @ W[128,64]
//    Block tile 128x64, 256 threads, 8x4 micro-tile per thread, K chunked by 32.
// ---------------------------------------------------------------------------
#define TILE_M 128
#define KC     32

__global__ __launch_bounds__(256) void gemm_kernel(const float* __restrict__ x,
                                                   const float* __restrict__ W) {
    __shared__ float xs[TILE_M][KC];    // 16 KB
    __shared__ float ws[KC][OUT_DIM];   // 8 KB

    const int tid   = threadIdx.x;
    const int base  = blockIdx.x * TILE_M;
    const int col_g = tid & 15;   // cols col_g*4 .. +3
    const int row_g = tid >> 4;   // rows row_g*8 .. +7

    float acc[8][4];
#pragma unroll
    for (int i = 0; i < 8; i++)
#pragma unroll
        for (int j = 0; j < 4; j++) acc[i][j] = 0.f;

    for (int kc = 0; kc < IN_DIM; kc += KC) {
#pragma unroll
        for (int t = 0; t < 4; t++) {
            int f = tid + 256 * t;            // 0..1023
            int r = f >> 3;                   // 0..127
            int c = (f & 7) * 4;              // 0..28
            int grow = base + r;
            float4 v = make_float4(0.f, 0.f, 0.f, 0.f);
            if (grow < N_NODES)
                v = __ldg((const float4*)(x + (size_t)grow * IN_DIM + kc + c));
            *(float4*)&xs[r][c] = v;
        }
#pragma unroll
        for (int t = 0; t < 2; t++) {
            int f  = tid + 256 * t;           // 0..511
            int kr = f >> 4;                  // 0..31
            int c  = (f & 15) * 4;            // 0..60
            float4 v = __ldg((const float4*)(W + (size_t)(kc + kr) * OUT_DIM + c));
            *(float4*)&ws[kr][c] = v;
        }
        __syncthreads();

#pragma unroll
        for (int k = 0; k < KC; k++) {
            float4 w4 = *(float4*)&ws[k][col_g * 4];
#pragma unroll
            for (int i = 0; i < 8; i++) {
                float xv = xs[row_g * 8 + i][k];
                acc[i][0] += xv * w4.x;
                acc[i][1] += xv * w4.y;
                acc[i][2] += xv * w4.z;
                acc[i][3] += xv * w4.w;
            }
        }
        __syncthreads();
    }

#pragma unroll
    for (int i = 0; i < 8; i++) {
        int r = base + row_g * 8 + i;
        if (r < N_NODES) {
            float4 v = make_float4(acc[i][0], acc[i][1], acc[i][2], acc[i][3]);
            *(float4*)(g_h + (size_t)r * OUT_DIM + col_g * 4) = v;
        }
    }
}

// ---------------------------------------------------------------------------
// 4) scatter: 16 threads per edge, one float4 of the 64-dim msg each.
//    out[col] += h[row] * dis[row]*dis[col]  (4 adjacent atomicAdds)
// ---------------------------------------------------------------------------
__global__ __launch_bounds__(256) void scatter_kernel(float* __restrict__ out) {
    int gid = blockIdx.x * blockDim.x + threadIdx.x;
    int e = gid >> 4;
    if (e >= N_EDGES) return;
    int j = gid & 15;

    int row = __ldg(&g_row[e]);
    int col = __ldg(&g_col[e]);
    float norm = __ldg(&g_dis[row]) * __ldg(&g_dis[col]);

    float4 v = __ldg((const float4*)(g_h + ((size_t)row << 6)) + j);
    v.x *= norm; v.y *= norm; v.z *= norm; v.w *= norm;

    float* p = out + ((size_t)col << 6) + (j << 2);
    atomicAdd(p + 0, v.x);
    atomicAdd(p + 1, v.y);
    atomicAdd(p + 2, v.z);
    atomicAdd(p + 3, v.w);
}

// ---------------------------------------------------------------------------
// 5) bias + relu, in place on out
// ---------------------------------------------------------------------------
__global__ void relu_bias_kernel(float* __restrict__ out, const float* __restrict__ b) {
    int i = blockIdx.x * blockDim.x + threadIdx.x;
    const int total4 = N_NODES * (OUT_DIM / 4);
    if (i >= total4) return;
    float4 v  = ((float4*)out)[i];
    float4 bv = __ldg((const float4*)b + (i & 15));
    v.x = fmaxf(v.x + bv.x, 0.f);
    v.y = fmaxf(v.y + bv.y, 0.f);
    v.z = fmaxf(v.z + bv.z, 0.f);
    v.w = fmaxf(v.w + bv.w, 0.f);
    ((float4*)out)[i] = v;
}

// ---------------------------------------------------------------------------
// Inputs resolved BY ELEMENT COUNT (unique):
//   x          : 12,800,000   edge_index : 3,200,000 (dtype auto-detected)
//   W          :      8,192   b          :        64
// ---------------------------------------------------------------------------
extern "C" void kernel_launch(void* const* d_in, const int* in_sizes, int n_in,
                              void* d_out, int out_size) {
    const float* x  = 0;
    const void*  ei = 0;
    const float* W  = 0;
    const float* b  = 0;

    for (int i = 0; i < n_in; i++) {
        int sz = in_sizes[i];
        if      (sz == N_NODES * IN_DIM)  x  = (const float*)d_in[i];
        else if (sz == 2 * N_EDGES)       ei = d_in[i];
        else if (sz == IN_DIM * OUT_DIM)  W  = (const float*)d_in[i];
        else if (sz == OUT_DIM)           b  = (const float*)d_in[i];
    }

    float* out = (float*)d_out;
    const int EB = (N_EDGES + 255) / 256;

    zero_kernel<<<6250, 256>>>(out);
    detect_kernel<<<EB, 256>>>((const int*)ei);
    convert_kernel<<<EB, 256>>>(ei);
    degree_kernel<<<EB, 256>>>();
    finalize_deg_kernel<<<(N_NODES + 255) / 256, 256>>>();
    gemm_kernel<<<(N_NODES + TILE_M - 1) / TILE_M, 256>>>(x, W);
    scatter_kernel<<<(N_EDGES * 16) / 256, 256>>>(out);
    relu_bias_kernel<<<(N_NODES * (OUT_DIM / 4) + 255) / 256, 256>>>(out, b);
}

// round 5
// speedup vs baseline: 2.2960x; 2.2960x over previous
#include <cuda_runtime.h>

#define N_NODES 100000
#define N_EDGES 1600000
#define IN_DIM  128
#define OUT_DIM 64

#define SCAN_BLK 1024
#define NB_SCAN ((N_NODES + SCAN_BLK - 1) / SCAN_BLK)   // 98

// Scratch (no allocations allowed).
__device__ float g_h[(size_t)N_NODES * OUT_DIM];   // h2 = (x@W)*dis[row], 25.6 MB
__device__ float g_dis[N_NODES];
__device__ int   g_row[N_EDGES];
__device__ int   g_col[N_EDGES];
__device__ int   g_cnt[N_NODES];                   // in-degree
__device__ int   g_off[N_NODES];                   // CSR offsets (exclusive scan)
__device__ int   g_cur[N_NODES];                   // bucket cursors
__device__ int   g_src[N_EDGES];                   // edges sorted by target
__device__ int   g_bsum[NB_SCAN];
__device__ int   g_is64;

// ---------------------------------------------------------------------------
// 0) reset counters (must happen every replay) + set dtype flag
// ---------------------------------------------------------------------------
__global__ void zero_kernel() {
    int i = blockIdx.x * blockDim.x + threadIdx.x;
    if (i == 0) g_is64 = 1;
    if (i < N_NODES) { g_cnt[i] = 0; g_cur[i] = 0; }
}

// ---------------------------------------------------------------------------
// 0b) dtype detect on first 1024 edges: int64 indices < 1e5 => hi word == 0.
//     Reads stay within first 8KB (in-bounds for either dtype).
// ---------------------------------------------------------------------------
__global__ void detect_kernel(const int* __restrict__ ei32) {
    int t = threadIdx.x;
    if (__ldg(&ei32[2 * t + 1]) != 0) g_is64 = 0;   // monotonic race: only writes 0
}

// ---------------------------------------------------------------------------
// 0c) materialize int32 row/col + count in-degree at targets
// ---------------------------------------------------------------------------
__global__ void convert_kernel(const void* __restrict__ ei) {
    int e = blockIdx.x * blockDim.x + threadIdx.x;
    if (e >= N_EDGES) return;
    int row, col;
    if (g_is64) {
        const long long* p = (const long long*)ei;
        row = (int)__ldg(&p[e]);
        col = (int)__ldg(&p[N_EDGES + e]);
    } else {
        const int* p = (const int*)ei;
        row = __ldg(&p[e]);
        col = __ldg(&p[N_EDGES + e]);
    }
    g_row[e] = row;
    g_col[e] = col;
    atomicAdd(&g_cnt[col], 1);
}

// ---------------------------------------------------------------------------
// 1) exclusive prefix scan of g_cnt -> g_off  (3 small kernels)
// ---------------------------------------------------------------------------
__global__ __launch_bounds__(SCAN_BLK) void scan1_kernel() {
    __shared__ int s[SCAN_BLK];
    int tid = threadIdx.x;
    int gid = blockIdx.x * SCAN_BLK + tid;
    int v = (gid < N_NODES) ? g_cnt[gid] : 0;
    s[tid] = v;
    __syncthreads();
#pragma unroll
    for (int d = 1; d < SCAN_BLK; d <<= 1) {
        int t = (tid >= d) ? s[tid - d] : 0;
        __syncthreads();
        s[tid] += t;
        __syncthreads();
    }
    if (gid < N_NODES) g_off[gid] = s[tid] - v;        // exclusive within block
    if (tid == SCAN_BLK - 1) g_bsum[blockIdx.x] = s[tid];
}

__global__ void scan2_kernel() {
    if (threadIdx.x == 0 && blockIdx.x == 0) {
        int run = 0;
        for (int i = 0; i < NB_SCAN; i++) { int t = g_bsum[i]; g_bsum[i] = run; run += t; }
    }
}

__global__ __launch_bounds__(SCAN_BLK) void scan3_kernel() {
    int gid = blockIdx.x * SCAN_BLK + threadIdx.x;
    if (gid < N_NODES) g_off[gid] += g_bsum[blockIdx.x];
}

// ---------------------------------------------------------------------------
// 2) dis = deg^{-1/2}
// ---------------------------------------------------------------------------
__global__ void dis_kernel() {
    int i = blockIdx.x * blockDim.x + threadIdx.x;
    if (i >= N_NODES) return;
    int c = g_cnt[i];
    g_dis[i] = (c > 0) ? rsqrtf((float)c) : 0.f;
}

// ---------------------------------------------------------------------------
// 3) GEMM: h2[N,64] = (x[N,128] @ W[128,64]) * dis[row]
// ---------------------------------------------------------------------------
#define TILE_M 128
#define KC     32

__global__ __launch_bounds__(256) void gemm_kernel(const float* __restrict__ x,
                                                   const float* __restrict__ W) {
    __shared__ float xs[TILE_M][KC];
    __shared__ float ws[KC][OUT_DIM];

    const int tid   = threadIdx.x;
    const int base  = blockIdx.x * TILE_M;
    const int col_g = tid & 15;
    const int row_g = tid >> 4;

    float acc[8][4];
#pragma unroll
    for (int i = 0; i < 8; i++)
#pragma unroll
        for (int j = 0; j < 4; j++) acc[i][j] = 0.f;

    for (int kc = 0; kc < IN_DIM; kc += KC) {
#pragma unroll
        for (int t = 0; t < 4; t++) {
            int f = tid + 256 * t;
            int r = f >> 3;
            int c = (f & 7) * 4;
            int grow = base + r;
            float4 v = make_float4(0.f, 0.f, 0.f, 0.f);
            if (grow < N_NODES)
                v = __ldg((const float4*)(x + (size_t)grow * IN_DIM + kc + c));
            *(float4*)&xs[r][c] = v;
        }
#pragma unroll
        for (int t = 0; t < 2; t++) {
            int f  = tid + 256 * t;
            int kr = f >> 4;
            int c  = (f & 15) * 4;
            float4 v = __ldg((const float4*)(W + (size_t)(kc + kr) * OUT_DIM + c));
            *(float4*)&ws[kr][c] = v;
        }
        __syncthreads();

#pragma unroll
        for (int k = 0; k < KC; k++) {
            float4 w4 = *(float4*)&ws[k][col_g * 4];
#pragma unroll
            for (int i = 0; i < 8; i++) {
                float xv = xs[row_g * 8 + i][k];
                acc[i][0] += xv * w4.x;
                acc[i][1] += xv * w4.y;
                acc[i][2] += xv * w4.z;
                acc[i][3] += xv * w4.w;
            }
        }
        __syncthreads();
    }

#pragma unroll
    for (int i = 0; i < 8; i++) {
        int r = base + row_g * 8 + i;
        if (r < N_NODES) {
            float d = g_dis[r];
            float4 v = make_float4(acc[i][0] * d, acc[i][1] * d,
                                   acc[i][2] * d, acc[i][3] * d);
            *(float4*)(g_h + (size_t)r * OUT_DIM + col_g * 4) = v;
        }
    }
}

// ---------------------------------------------------------------------------
// 4) bucket fill: sort edge sources by target node (CSR)
// ---------------------------------------------------------------------------
__global__ void fill_kernel() {
    int e = blockIdx.x * blockDim.x + threadIdx.x;
    if (e >= N_EDGES) return;
    int col = g_col[e];
    int pos = g_off[col] + atomicAdd(&g_cur[col], 1);
    g_src[pos] = g_row[e];
}

// ---------------------------------------------------------------------------
// 5) aggregate: one warp per target node, register accumulation, no atomics.
//    out[node] = relu( dis[node] * sum_{src} h2[src] + b )
// ---------------------------------------------------------------------------
__global__ __launch_bounds__(256) void agg_kernel(float* __restrict__ out,
                                                  const float* __restrict__ b) {
    int node = (blockIdx.x * blockDim.x + threadIdx.x) >> 5;
    int lane = threadIdx.x & 31;
    if (node >= N_NODES) return;

    int beg = g_off[node];
    int n   = g_cnt[node];

    float2 acc = make_float2(0.f, 0.f);
#pragma unroll 4
    for (int k = 0; k < n; k++) {
        int src = __ldg(&g_src[beg + k]);
        float2 v = __ldg((const float2*)(g_h + ((size_t)src << 6)) + lane);
        acc.x += v.x;
        acc.y += v.y;
    }

    float dc  = g_dis[node];
    float2 bb = __ldg((const float2*)b + lane);
    float2 o;
    o.x = fmaxf(acc.x * dc + bb.x, 0.f);
    o.y = fmaxf(acc.y * dc + bb.y, 0.f);
    ((float2*)(out + ((size_t)node << 6)))[lane] = o;
}

// ---------------------------------------------------------------------------
// Inputs resolved BY ELEMENT COUNT (unique):
//   x: 12,800,000   edge_index: 3,200,000 (dtype auto-detected)
//   W: 8,192        b: 64
// ---------------------------------------------------------------------------
extern "C" void kernel_launch(void* const* d_in, const int* in_sizes, int n_in,
                              void* d_out, int out_size) {
    const float* x  = 0;
    const void*  ei = 0;
    const float* W  = 0;
    const float* b  = 0;

    for (int i = 0; i < n_in; i++) {
        int sz = in_sizes[i];
        if      (sz == N_NODES * IN_DIM)  x  = (const float*)d_in[i];
        else if (sz == 2 * N_EDGES)       ei = d_in[i];
        else if (sz == IN_DIM * OUT_DIM)  W  = (const float*)d_in[i];
        else if (sz == OUT_DIM)           b  = (const float*)d_in[i];
    }

    float* out = (float*)d_out;
    const int EB = (N_EDGES + 255) / 256;
    const int NBn = (N_NODES + 255) / 256;

    zero_kernel<<<NBn, 256>>>();
    detect_kernel<<<1, 1024>>>((const int*)ei);
    convert_kernel<<<EB, 256>>>(ei);
    scan1_kernel<<<NB_SCAN, SCAN_BLK>>>();
    scan2_kernel<<<1, 32>>>();
    scan3_kernel<<<NB_SCAN, SCAN_BLK>>>();
    dis_kernel<<<NBn, 256>>>();
    gemm_kernel<<<(N_NODES + TILE_M - 1) / TILE_M, 256>>>(x, W);
    fill_kernel<<<EB, 256>>>();
    agg_kernel<<<(N_NODES * 32 + 255) / 256, 256>>>(out, b);
}

// round 10
// speedup vs baseline: 2.6212x; 1.1416x over previous
#include <cuda_runtime.h>
#include <cstdint>

#define N_NODES 100000
#define N_EDGES 1600000
#define IN_DIM  128
#define OUT_DIM 64

#define SCAN_BLK 1024
#define NB_SCAN ((N_NODES + SCAN_BLK - 1) / SCAN_BLK)   // 98

// Scratch (no allocations allowed).
__device__ float g_h[(size_t)N_NODES * OUT_DIM];   // h2 = (x@W)*dis[row], 25.6 MB
__device__ float g_dis[N_NODES];
__device__ int   g_row[N_EDGES];
__device__ int   g_col[N_EDGES];
__device__ int   g_cnt[N_NODES];
__device__ int   g_off[N_NODES];
__device__ int   g_cur[N_NODES];
__device__ int   g_src[N_EDGES];
__device__ int   g_bsum[NB_SCAN];
__device__ int   g_is64;

// ---------------------------------------------------------------------------
// 0) reset counters + dtype flag
// ---------------------------------------------------------------------------
__global__ void zero_kernel() {
    int i = blockIdx.x * blockDim.x + threadIdx.x;
    if (i == 0) g_is64 = 1;
    if (i < N_NODES) { g_cnt[i] = 0; g_cur[i] = 0; }
}

// 0b) dtype detect (first 1024 edges; in-bounds for either dtype)
__global__ void detect_kernel(const int* __restrict__ ei32) {
    int t = threadIdx.x;
    if (__ldg(&ei32[2 * t + 1]) != 0) g_is64 = 0;
}

// 0c) materialize int32 row/col + in-degree count
__global__ void convert_kernel(const void* __restrict__ ei) {
    int e = blockIdx.x * blockDim.x + threadIdx.x;
    if (e >= N_EDGES) return;
    int row, col;
    if (g_is64) {
        const long long* p = (const long long*)ei;
        row = (int)__ldg(&p[e]);
        col = (int)__ldg(&p[N_EDGES + e]);
    } else {
        const int* p = (const int*)ei;
        row = __ldg(&p[e]);
        col = __ldg(&p[N_EDGES + e]);
    }
    g_row[e] = row;
    g_col[e] = col;
    atomicAdd(&g_cnt[col], 1);
}

// ---------------------------------------------------------------------------
// 1) exclusive prefix scan of g_cnt -> g_off
// ---------------------------------------------------------------------------
__global__ __launch_bounds__(SCAN_BLK) void scan1_kernel() {
    __shared__ int s[SCAN_BLK];
    int tid = threadIdx.x;
    int gid = blockIdx.x * SCAN_BLK + tid;
    int v = (gid < N_NODES) ? g_cnt[gid] : 0;
    s[tid] = v;
    __syncthreads();
#pragma unroll
    for (int d = 1; d < SCAN_BLK; d <<= 1) {
        int t = (tid >= d) ? s[tid - d] : 0;
        __syncthreads();
        s[tid] += t;
        __syncthreads();
    }
    if (gid < N_NODES) g_off[gid] = s[tid] - v;
    if (tid == SCAN_BLK - 1) g_bsum[blockIdx.x] = s[tid];
}

__global__ void scan2_kernel() {
    if (threadIdx.x == 0 && blockIdx.x == 0) {
        int run = 0;
        for (int i = 0; i < NB_SCAN; i++) { int t = g_bsum[i]; g_bsum[i] = run; run += t; }
    }
}

// scan3 + dis fused: finalize offsets and compute deg^{-1/2}
__global__ __launch_bounds__(SCAN_BLK) void scan3_kernel() {
    int gid = blockIdx.x * SCAN_BLK + threadIdx.x;
    if (gid < N_NODES) {
        g_off[gid] += g_bsum[blockIdx.x];
        int c = g_cnt[gid];
        g_dis[gid] = (c > 0) ? rsqrtf((float)c) : 0.f;
    }
}

// ---------------------------------------------------------------------------
// 2) GEMM via legacy mma.sync tf32 (baseline PTX, works on plain sm_103):
//    h2[128,64] = (x_tile[128,128] @ W[128,64]) * dis[row]
//    Block: 128 threads / 4 warps; warp w owns rows w*32..w*32+31.
//    Per warp: 2 (m16) x 8 (n8) x 16 (k8 steps) mma.m16n8k8.tf32.
// ---------------------------------------------------------------------------
#define APITCH 132
#define BPITCH 68
#define GSMEM ((128 * APITCH + 128 * BPITCH) * 4)   // 102400 bytes

__global__ __launch_bounds__(128) void gemm_mma_kernel(const float* __restrict__ x,
                                                       const float* __restrict__ W) {
    extern __shared__ float sm[];
    float* As = sm;                    // [128][APITCH]
    float* Bs = sm + 128 * APITCH;     // [128][BPITCH]  (k-major: Bs[k][n])

    const int tid  = threadIdx.x;
    const int lane = tid & 31;
    const int w    = tid >> 5;
    const int base = blockIdx.x * 128;
    const int nvalid = min(128, N_NODES - base);

    // ---- stage W (128x64) as tf32 bits ----
#pragma unroll
    for (int t = 0; t < 16; t++) {
        int i = t * 128 + tid;          // float4 index 0..2047
        int r = i >> 4;                 // k row 0..127
        int c = (i & 15) * 4;           // n col
        float4 v = __ldg((const float4*)(W + r * OUT_DIM + c));
        uint32_t u0, u1, u2, u3;
        asm("cvt.rna.tf32.f32 %0, %1;" : "=r"(u0) : "f"(v.x));
        asm("cvt.rna.tf32.f32 %0, %1;" : "=r"(u1) : "f"(v.y));
        asm("cvt.rna.tf32.f32 %0, %1;" : "=r"(u2) : "f"(v.z));
        asm("cvt.rna.tf32.f32 %0, %1;" : "=r"(u3) : "f"(v.w));
        float* d = Bs + r * BPITCH + c;
        d[0] = __uint_as_float(u0); d[1] = __uint_as_float(u1);
        d[2] = __uint_as_float(u2); d[3] = __uint_as_float(u3);
    }

    // ---- stage x tile (128x128) as tf32 bits, zero-pad invalid rows ----
#pragma unroll
    for (int t = 0; t < 32; t++) {
        int i = t * 128 + tid;          // float4 index 0..4095
        int r = i >> 5;                 // row 0..127
        int c = (i & 31) * 4;           // col
        float4 v = make_float4(0.f, 0.f, 0.f, 0.f);
        if (r < nvalid)
            v = __ldg((const float4*)(x + ((size_t)(base + r) << 7) + c));
        uint32_t u0, u1, u2, u3;
        asm("cvt.rna.tf32.f32 %0, %1;" : "=r"(u0) : "f"(v.x));
        asm("cvt.rna.tf32.f32 %0, %1;" : "=r"(u1) : "f"(v.y));
        asm("cvt.rna.tf32.f32 %0, %1;" : "=r"(u2) : "f"(v.z));
        asm("cvt.rna.tf32.f32 %0, %1;" : "=r"(u3) : "f"(v.w));
        float* d = As + r * APITCH + c;
        d[0] = __uint_as_float(u0); d[1] = __uint_as_float(u1);
        d[2] = __uint_as_float(u2); d[3] = __uint_as_float(u3);
    }
    __syncthreads();

    float acc[2][8][4];
#pragma unroll
    for (int mi = 0; mi < 2; mi++)
#pragma unroll
        for (int ni = 0; ni < 8; ni++)
#pragma unroll
            for (int j = 0; j < 4; j++) acc[mi][ni][j] = 0.f;

    const int arow = w * 32 + (lane >> 2);   // A fragment base row
    const int acol = lane & 3;               // A fragment base col (k)
    const int bcol = lane >> 2;              // B fragment col (n within tile)
    const int bkof = lane & 3;               // B fragment row (k within step)

#pragma unroll
    for (int kk = 0; kk < 16; kk++) {
        int kb = kk * 8;
        uint32_t a[2][4];
#pragma unroll
        for (int mi = 0; mi < 2; mi++) {
            const float* ap = As + (arow + mi * 16) * APITCH + kb + acol;
            a[mi][0] = __float_as_uint(ap[0]);
            a[mi][1] = __float_as_uint(ap[8 * APITCH]);
            a[mi][2] = __float_as_uint(ap[4]);
            a[mi][3] = __float_as_uint(ap[8 * APITCH + 4]);
        }
        uint32_t bf[8][2];
#pragma unroll
        for (int ni = 0; ni < 8; ni++) {
            const float* bp = Bs + (kb + bkof) * BPITCH + ni * 8 + bcol;
            bf[ni][0] = __float_as_uint(bp[0]);
            bf[ni][1] = __float_as_uint(bp[4 * BPITCH]);
        }
#pragma unroll
        for (int mi = 0; mi < 2; mi++)
#pragma unroll
            for (int ni = 0; ni < 8; ni++) {
                asm volatile(
                    "mma.sync.aligned.m16n8k8.row.col.f32.tf32.tf32.f32 "
                    "{%0, %1, %2, %3}, {%4, %5, %6, %7}, {%8, %9}, {%0, %1, %2, %3};"
                    : "+f"(acc[mi][ni][0]), "+f"(acc[mi][ni][1]),
                      "+f"(acc[mi][ni][2]), "+f"(acc[mi][ni][3])
                    : "r"(a[mi][0]), "r"(a[mi][1]), "r"(a[mi][2]), "r"(a[mi][3]),
                      "r"(bf[ni][0]), "r"(bf[ni][1]));
            }
    }

    // ---- epilogue: scale by dis[row], write g_h ----
    const int cc = 2 * (lane & 3);
#pragma unroll
    for (int mi = 0; mi < 2; mi++) {
        int ra = base + w * 32 + mi * 16 + (lane >> 2);
        int rb = ra + 8;
        float da = (ra < N_NODES) ? __ldg(&g_dis[ra]) : 0.f;
        float db = (rb < N_NODES) ? __ldg(&g_dis[rb]) : 0.f;
#pragma unroll
        for (int ni = 0; ni < 8; ni++) {
            if (ra < N_NODES) {
                float2 o = make_float2(acc[mi][ni][0] * da, acc[mi][ni][1] * da);
                *(float2*)(g_h + ((size_t)ra << 6) + ni * 8 + cc) = o;
            }
            if (rb < N_NODES) {
                float2 o = make_float2(acc[mi][ni][2] * db, acc[mi][ni][3] * db);
                *(float2*)(g_h + ((size_t)rb << 6) + ni * 8 + cc) = o;
            }
        }
    }
}

// ---------------------------------------------------------------------------
// 3) bucket fill (CSR by target)
// ---------------------------------------------------------------------------
__global__ void fill_kernel() {
    int e = blockIdx.x * blockDim.x + threadIdx.x;
    if (e >= N_EDGES) return;
    int col = g_col[e];
    int pos = g_off[col] + atomicAdd(&g_cur[col], 1);
    g_src[pos] = g_row[e];
}

// ---------------------------------------------------------------------------
// 4) aggregate: one warp per target node, register accumulation, no atomics
// ---------------------------------------------------------------------------
__global__ __launch_bounds__(256) void agg_kernel(float* __restrict__ out,
                                                  const float* __restrict__ b) {
    int node = (blockIdx.x * blockDim.x + threadIdx.x) >> 5;
    int lane = threadIdx.x & 31;
    if (node >= N_NODES) return;

    int beg = g_off[node];
    int n   = g_cnt[node];

    float2 acc = make_float2(0.f, 0.f);
#pragma unroll 4
    for (int k = 0; k < n; k++) {
        int src = __ldg(&g_src[beg + k]);
        float2 v = __ldg((const float2*)(g_h + ((size_t)src << 6)) + lane);
        acc.x += v.x;
        acc.y += v.y;
    }

    float dc  = g_dis[node];
    float2 bb = __ldg((const float2*)b + lane);
    float2 o;
    o.x = fmaxf(acc.x * dc + bb.x, 0.f);
    o.y = fmaxf(acc.y * dc + bb.y, 0.f);
    ((float2*)(out + ((size_t)node << 6)))[lane] = o;
}

// ---------------------------------------------------------------------------
extern "C" void kernel_launch(void* const* d_in, const int* in_sizes, int n_in,
                              void* d_out, int out_size) {
    const float* x  = 0;
    const void*  ei = 0;
    const float* W  = 0;
    const float* b  = 0;

    for (int i = 0; i < n_in; i++) {
        int sz = in_sizes[i];
        if      (sz == N_NODES * IN_DIM)  x  = (const float*)d_in[i];
        else if (sz == 2 * N_EDGES)       ei = d_in[i];
        else if (sz == IN_DIM * OUT_DIM)  W  = (const float*)d_in[i];
        else if (sz == OUT_DIM)           b  = (const float*)d_in[i];
    }

    float* out = (float*)d_out;
    const int EB  = (N_EDGES + 255) / 256;
    const int NBn = (N_NODES + 255) / 256;
    const int GB  = (N_NODES + 127) / 128;   // 782

    static int smem_set = 0;
    if (!smem_set) {
        cudaFuncSetAttribute(gemm_mma_kernel,
                             cudaFuncAttributeMaxDynamicSharedMemorySize, GSMEM);
        smem_set = 1;
    }

    zero_kernel<<<NBn, 256>>>();
    detect_kernel<<<1, 1024>>>((const int*)ei);
    convert_kernel<<<EB, 256>>>(ei);
    scan1_kernel<<<NB_SCAN, SCAN_BLK>>>();
    scan2_kernel<<<1, 32>>>();
    scan3_kernel<<<NB_SCAN, SCAN_BLK>>>();
    gemm_mma_kernel<<<GB, 128, GSMEM>>>(x, W);
    fill_kernel<<<EB, 256>>>();
    agg_kernel<<<(N_NODES * 32 + 255) / 256, 256>>>(out, b);
}